// round 1
// baseline (speedup 1.0000x reference)
#include <cuda_runtime.h>
#include <cuda_bf16.h>

// CTC batch cost (keras ctc_batch_cost semantics), forward only.
// B=512, T=512, C=128, L=32, S=65, blank=C-1.
//
// Strategy:
//   - 1 CTA per batch element, 128 threads.
//   - Warp 0: alpha recursion. Lane l owns s=2l (even, blank) and s=2l+1 (label);
//     lane 31 additionally owns s=64 (final blank, purely lane-local).
//     Only cross-lane traffic per step: one shfl_up of a1 (alpha at odd positions).
//   - Warps 1..3 (96 threads): gather log(y_pred[b,t,ext[s]] + 1e-7) for the NEXT
//     64-timestep chunk into double-buffered shared memory. One __syncthreads per
//     chunk handoff; recursion inner loop is barrier-free.

#define NEGINF (-1e30f)

namespace {
constexpr int Bsz = 512;
constexpr int Tsz = 512;
constexpr int Csz = 128;
constexpr int Lsz = 32;
constexpr int Ssz = 2 * Lsz + 1;   // 65
constexpr int TC  = 64;            // timesteps per chunk
constexpr int NCH = Tsz / TC;      // 8 chunks
constexpr int SPAD = Ssz + 1;      // 66, keeps float2 rows 8B-aligned
}

__global__ __launch_bounds__(128, 4)
void ctc_loss_kernel(const int* __restrict__ y_true,
                     const float* __restrict__ y_pred,
                     float* __restrict__ out)
{
    __shared__ int   lab[Lsz];
    __shared__ float lp[2][TC][SPAD];

    const int b    = blockIdx.x;
    const int tid  = threadIdx.x;
    const int lane = tid & 31;

    if (tid < Lsz) lab[tid] = y_true[b * Lsz + tid];
    __syncthreads();

    // ---- producer: gather log-probs of extended labels for one chunk ----
    auto loadChunk = [&](int c, int bi) {
        const float* base = y_pred + ((long)b * Tsz + (long)c * TC) * Csz;
        for (int idx = tid - 32; idx < TC * Ssz; idx += 96) {
            int t = idx / Ssz;
            int s = idx - t * Ssz;
            int cls = (s & 1) ? lab[s >> 1] : (Csz - 1);
            float v = base[t * Csz + cls];
            lp[bi][t][s] = __logf(v + 1e-7f);
        }
    };

    if (tid >= 32) loadChunk(0, 0);
    __syncthreads();

    // ---- recursion state (warp 0) ----
    float a0 = NEGINF, a1 = NEGINF, a2 = NEGINF;
    bool skip1 = false;
    if (tid < 32) {
        int myl = lab[lane];
        int pl  = (lane > 0) ? lab[lane - 1] : -1;
        // skip allowed at s=2*lane+1 iff lane>=1, label differs from previous
        // label, and label != blank (labels are < C-1 by construction anyway).
        skip1 = (lane >= 1) && (myl != pl) && (myl != Csz - 1);
    }

    for (int c = 0; c < NCH; ++c) {
        if (tid < 32) {
            const int bi = c & 1;
            #pragma unroll 4
            for (int tt = 0; tt < TC; ++tt) {
                const float* row = &lp[bi][tt][0];
                float2 l01 = *(const float2*)(row + 2 * lane);
                float  l2  = row[64];   // broadcast; used by lane 31 only

                if (c == 0 && tt == 0) {
                    // alpha init at t=0: only s=0 and s=1 active
                    a0 = (lane == 0) ? l01.x : NEGINF;
                    a1 = (lane == 0) ? l01.y : NEGINF;
                    a2 = NEGINF;
                } else {
                    // p1 = alpha[2*lane - 1] (previous odd position)
                    float p1 = __shfl_up_sync(0xffffffffu, a1, 1);
                    if (lane == 0) p1 = NEGINF;

                    float a0o = a0, a1o = a1;

                    // even s=2l (blank, no skip): lse2(a0o, p1) + lp
                    float m0 = fmaxf(a0o, p1);
                    float d0 = fabsf(a0o - p1);
                    a0 = m0 + __logf(1.0f + __expf(-d0)) + l01.x;

                    // odd s=2l+1: lse3(a1o, a0o, skip ? p1 : -inf) + lp
                    float zv = skip1 ? p1 : NEGINF;
                    float m1 = fmaxf(fmaxf(a1o, a0o), zv);
                    float e1 = __expf(a1o - m1) + __expf(a0o - m1) + __expf(zv - m1);
                    a1 = m1 + __logf(e1) + l01.y;

                    // s=64 (final blank): lse2(a2, a1o) + lp, lane-31 local
                    float m2 = fmaxf(a2, a1o);
                    float d2 = fabsf(a2 - a1o);
                    float n2 = m2 + __logf(1.0f + __expf(-d2)) + l2;
                    if (lane == 31) a2 = n2;
                }
            }
        } else if (c + 1 < NCH) {
            loadChunk(c + 1, (c + 1) & 1);
        }
        __syncthreads();
    }

    // log P = lse(alpha_T[S-1], alpha_T[S-2]) = lse2(a2, a1) on lane 31
    if (tid == 31) {
        float m = fmaxf(a2, a1);
        float d = fabsf(a2 - a1);
        out[b] = -(m + __logf(1.0f + __expf(-d)));
    }
}

extern "C" void kernel_launch(void* const* d_in, const int* in_sizes, int n_in,
                              void* d_out, int out_size)
{
    const int*   y_true = (const int*)d_in[0];    // [512, 32] int32
    const float* y_pred = (const float*)d_in[1];  // [512, 512, 128] float32
    float*       out    = (float*)d_out;          // [512, 1] float32
    (void)in_sizes; (void)n_in; (void)out_size;

    ctc_loss_kernel<<<Bsz, 128>>>(y_true, y_pred, out);
}

// round 2
// speedup vs baseline: 3.6397x; 3.6397x over previous
#include <cuda_runtime.h>
#include <cuda_bf16.h>

// CTC batch cost, B=512 T=512 C=128 L=32, S=65, blank=127.
// Per-CTA: 1 recursion warp (id = blockIdx.x & 3, spreads across SMSPs),
// 3 loader warps streaming full probability rows (coalesced float4) into a
// double-buffered SMEM tile. Recursion gathers label/blank probs from SMEM
// and runs the alpha recursion in log2 domain.
//
// Lane mapping: lane l owns s=2l (blank) and s=2l+1 (label l).
// rotate-shfl of a1: lane l gets alpha[2l-1]; lane 0 gets alpha[63], which it
// uses to update s=64 (reusing the even-position lse2 unit; s=0 update is the
// exact a0 += lp_blank since s=0 has no predecessor).

#define NEGINF (-1e30f)

namespace {
constexpr int Bsz = 512;
constexpr int Tsz = 512;
constexpr int Csz = 128;
constexpr int Lsz = 32;
constexpr int TC  = 32;            // timesteps per chunk
constexpr int NCH = Tsz / TC;      // 16 chunks
constexpr float LN2F = 0.69314718055994530942f;
}

__device__ __forceinline__ float ex2f_(float x) {
    float r; asm("ex2.approx.ftz.f32 %0, %1;" : "=f"(r) : "f"(x)); return r;
}
__device__ __forceinline__ float lg2f_(float x) {
    float r; asm("lg2.approx.ftz.f32 %0, %1;" : "=f"(r) : "f"(x)); return r;
}

__global__ __launch_bounds__(128, 4)
void ctc_loss_kernel(const int* __restrict__ y_true,
                     const float* __restrict__ y_pred,
                     float* __restrict__ out)
{
    __shared__ float4 raw4[2][TC * (Csz / 4)];   // 2 x 32 x 128 floats = 32 KB
    __shared__ int    lab[Lsz];

    const int b    = blockIdx.x;
    const int tid  = threadIdx.x;
    const int wid  = tid >> 5;
    const int lane = tid & 31;
    const int rw   = b & 3;            // recursion warp id (spread over SMSPs)

    if (tid < Lsz) lab[tid] = y_true[b * Lsz + tid];
    __syncthreads();

    const bool isComp = (wid == rw);
    int lrank = 0;
    if (!isComp) lrank = ((wid > rw) ? wid - 1 : wid) * 32 + lane;  // 0..95

    auto loadChunk = [&](int c) {
        const float4* src = (const float4*)(y_pred + ((long)b * Tsz + (long)c * TC) * Csz);
        float4* dst = raw4[c & 1];
        for (int i = lrank; i < TC * (Csz / 4); i += 96) dst[i] = src[i];
    };

    if (!isComp) loadChunk(0);
    __syncthreads();

    // recursion state (log2 domain)
    float a0 = NEGINF, a1 = NEGINF, a2 = NEGINF;
    int myLab = 0, laneSrc = 0;
    bool skip1 = false;
    if (isComp) {
        myLab = lab[lane];
        int pl = (lane > 0) ? lab[lane - 1] : -1;
        skip1 = (lane >= 1) && (myLab != pl);   // labels are never blank
        laneSrc = (lane + 31) & 31;             // rotate: lane l <- lane (l-1)%32
    }

    for (int c = 0; c < NCH; ++c) {
        if (isComp) {
            const float* rawf = (const float*)raw4[c & 1];
            int t0 = 0;
            if (c == 0) {
                float vb = rawf[Csz - 1], vl = rawf[myLab];
                float lpb = lg2f_(vb + 1e-7f), lpl = lg2f_(vl + 1e-7f);
                a0 = (lane == 0) ? lpb : NEGINF;
                a1 = (lane == 0) ? lpl : NEGINF;
                a2 = NEGINF;
                t0 = 1;
            }
            #pragma unroll 8
            for (int tt = t0; tt < TC; ++tt) {
                const float* row = rawf + tt * Csz;
                float vb = row[Csz - 1];           // blank prob (broadcast LDS)
                float vl = row[myLab];             // label prob (scattered LDS)
                float lpb = lg2f_(vb + 1e-7f);
                float lpl = lg2f_(vl + 1e-7f);

                float rot = __shfl_sync(0xffffffffu, a1, laneSrc);
                float a0o = a0, a1o = a1;

                // shared lse2 unit:
                //  lanes>=1: a0 = lse2(a0o, alpha[2l-1]) + lpb
                //  lane 0  : a2 = lse2(a2,  alpha[63])   + lpb ; a0 = a0o + lpb
                float x  = (lane == 0) ? a2 : a0o;
                float m0 = fmaxf(x, rot);
                float d0 = fabsf(x - rot);
                float r0 = m0 + lg2f_(1.0f + ex2f_(-d0)) + lpb;
                if (lane == 0) { a2 = r0; a0 = a0o + lpb; }
                else           { a0 = r0; }

                // odd: a1 = lse3(a1o, a0o, skip ? alpha[2l-1] : -inf) + lpl
                float zv = skip1 ? rot : NEGINF;   // skip1 is false on lane 0
                float m1 = fmaxf(fmaxf(a1o, a0o), zv);
                float e  = ex2f_(a1o - m1) + ex2f_(a0o - m1) + ex2f_(zv - m1);
                a1 = m1 + lg2f_(e) + lpl;
            }
        } else if (c + 1 < NCH) {
            loadChunk(c + 1);
        }
        __syncthreads();
    }

    if (isComp) {
        float a1_31 = __shfl_sync(0xffffffffu, a1, 31);   // alpha_T[S-2]
        if (lane == 0) {
            float m = fmaxf(a2, a1_31);
            float d = fabsf(a2 - a1_31);
            out[b] = -LN2F * (m + lg2f_(1.0f + ex2f_(-d)));
        }
    }
}

extern "C" void kernel_launch(void* const* d_in, const int* in_sizes, int n_in,
                              void* d_out, int out_size)
{
    const int*   y_true = (const int*)d_in[0];    // [512, 32] int32
    const float* y_pred = (const float*)d_in[1];  // [512, 512, 128] float32
    float*       out    = (float*)d_out;          // [512, 1] float32
    (void)in_sizes; (void)n_in; (void)out_size;

    ctc_loss_kernel<<<Bsz, 128>>>(y_true, y_pred, out);
}

// round 4
// speedup vs baseline: 4.1172x; 1.1312x over previous
#include <cuda_runtime.h>
#include <cuda_bf16.h>

// CTC batch cost, B=512 T=512 C=128 L=32, S=65, blank=127.
// Probability-domain forward recursion with PER-LANE power-of-two exponent
// frames (renormalized every 32-step chunk): zero MUFU on the critical path.
// 1 recursion warp per CTA (id = blockIdx.x & 3), 3 loader warps streaming
// full probability rows (float4, .cs) into double-buffered SMEM.
//
// Lane l owns s=2l (blank) and s=2l+1 (label l); rotate-shfl of a1 gives
// lane l alpha[2l-1]; lane 0 receives alpha[63] for the s=64 update (a2).
// Cross-lane values are rescaled by scaleRot = 2^(shift_src - shift_own),
// recomputed once per chunk from the per-lane frame exponents.

namespace {
constexpr int Bsz = 512;
constexpr int Tsz = 512;
constexpr int Csz = 128;
constexpr int Lsz = 32;
constexpr int TC  = 32;            // timesteps per chunk
constexpr int NCH = Tsz / TC;      // 16 chunks
constexpr float LN2F = 0.69314718055994530942f;
constexpr float EPSF = 1e-7f;
}

__device__ __forceinline__ float ex2f_(float x) {
    float r; asm("ex2.approx.ftz.f32 %0, %1;" : "=f"(r) : "f"(x)); return r;
}
__device__ __forceinline__ float lg2f_(float x) {
    float r; asm("lg2.approx.ftz.f32 %0, %1;" : "=f"(r) : "f"(x)); return r;
}

__global__ __launch_bounds__(128, 4)
void ctc_loss_kernel(const int* __restrict__ y_true,
                     const float* __restrict__ y_pred,
                     float* __restrict__ out)
{
    __shared__ float4 raw4[2][TC * (Csz / 4)];   // 2 x 32 x 128 floats = 32 KB
    __shared__ int    lab[Lsz];

    const int b    = blockIdx.x;
    const int tid  = threadIdx.x;
    const int wid  = tid >> 5;
    const int lane = tid & 31;
    const int rw   = b & 3;            // recursion warp id (spread over SMSPs)

    if (tid < Lsz) lab[tid] = y_true[b * Lsz + tid];
    __syncthreads();

    const bool isComp = (wid == rw);
    int lrank = 0;
    if (!isComp) lrank = ((wid > rw) ? wid - 1 : wid) * 32 + lane;  // 0..95

    auto loadChunk = [&](int c) {
        const float4* src = (const float4*)(y_pred + ((long)b * Tsz + (long)c * TC) * Csz);
        float4* dst = raw4[c & 1];
        for (int i = lrank; i < TC * (Csz / 4); i += 96) dst[i] = __ldcs(src + i);
    };

    if (!isComp) loadChunk(0);
    __syncthreads();

    // recursion state (probability domain, per-lane frames)
    float a0 = 0.0f, a1 = 0.0f, a2 = 0.0f;
    float skipM = 0.0f, scaleRot = 1.0f;
    int   myLab = 0, laneSrc = 0, shift = 0;
    if (isComp) {
        myLab   = lab[lane];
        skipM   = (lane >= 1 && myLab != lab[lane - 1]) ? 1.0f : 0.0f;
        laneSrc = (lane + 31) & 31;    // rotate: lane l <- lane (l-1)%32
    }

    for (int c = 0; c < NCH; ++c) {
        if (isComp) {
            const float* rawf = (const float*)raw4[c & 1];
            int t0 = 0;
            if (c == 0) {
                float pb = rawf[Csz - 1] + EPSF;
                float pl = rawf[myLab]   + EPSF;
                a0 = (lane == 0) ? pb : 0.0f;
                a1 = (lane == 0) ? pl : 0.0f;
                t0 = 1;
            }
            #pragma unroll 8
            for (int tt = t0; tt < TC; ++tt) {
                const float* row = rawf + tt * Csz;
                float pb = row[Csz - 1] + EPSF;   // blank prob (broadcast LDS)
                float pl = row[myLab]   + EPSF;   // label prob (scattered LDS)

                float rot = __shfl_sync(0xffffffffu, a1, laneSrc) * scaleRot;
                float tsum = a1 + a0;

                // even-slot unit: lanes>=1 update a0; lane 0 updates a2 (s=64)
                float x  = (lane == 0) ? a2 : a0;
                float r0 = (x + rot) * pb;

                // odd: a1 = (a1 + a0 + skip*alpha[2l-1]) * pl
                a1 = __fmaf_rn(rot, skipM, tsum) * pl;

                if (lane == 0) { a2 = r0; a0 = a0 * pb; }
                else           { a0 = r0; }
            }

            // ---- per-lane renorm + frame exchange (every 32 steps) ----
            float m = fmaxf(fmaxf(a0, a1), a2);   // a2==0 on lanes != 0
            int e = 0;
            if (m > 0.0f) e = (int)(__float_as_uint(m) >> 23) - 127;
            if (e > 126) e = 126;                  // paranoia; never triggers
            float sc = __uint_as_float((unsigned)(127 - e) << 23);  // exact 2^-e
            a0 *= sc; a1 *= sc; a2 *= sc;
            shift += e;

            int shSrc = __shfl_sync(0xffffffffu, shift, laneSrc);
            if (m == 0.0f) shift = shSrc;          // dead lane adopts source frame
            int d = shSrc - shift;
            d = (d > 126) ? 126 : d;
            scaleRot = (d < -126) ? 0.0f
                     : __uint_as_float((unsigned)(127 + d) << 23);  // exact 2^d
        } else if (c + 1 < NCH) {
            loadChunk(c + 1);
        }
        __syncthreads();
    }

    if (isComp) {
        // log2 of alpha_T[S-1] (lane 0: a2) and alpha_T[S-2] (lane 31: a1)
        float v  = lg2f_((lane == 31) ? a1 : a2) + (float)shift;
        float v1 = __shfl_sync(0xffffffffu, v, 31);
        if (lane == 0) {
            float mm = fmaxf(v, v1);
            float dd = fabsf(v - v1);
            out[b] = -LN2F * (mm + lg2f_(1.0f + ex2f_(-dd)));
        }
    }
}

extern "C" void kernel_launch(void* const* d_in, const int* in_sizes, int n_in,
                              void* d_out, int out_size)
{
    const int*   y_true = (const int*)d_in[0];    // [512, 32] int32
    const float* y_pred = (const float*)d_in[1];  // [512, 512, 128] float32
    float*       out    = (float*)d_out;          // [512, 1] float32
    (void)in_sizes; (void)n_in; (void)out_size;

    ctc_loss_kernel<<<Bsz, 128>>>(y_true, y_pred, out);
}

// round 6
// speedup vs baseline: 6.6671x; 1.6193x over previous
#include <cuda_runtime.h>
#include <cuda_bf16.h>
#include <cstdint>

// CTC batch cost, B=512 T=512 C=128 L=32, S=65, blank=127.
// Probability-domain forward recursion, per-lane power-of-two exponent frames
// (renorm every 32 steps). 1 recursion warp per CTA (spread across SMSPs via
// (b/148)&3), 3 loader warps feeding a 4-stage cp.async.cg ring (TC=16 rows
// per stage) so load latency is fully decoupled from the serial alpha chain.

namespace {
constexpr int Bsz = 512;
constexpr int Tsz = 512;
constexpr int Csz = 128;
constexpr int Lsz = 32;
constexpr int TC   = 16;            // timesteps per stage
constexpr int NCH  = Tsz / TC;      // 32 chunks
constexpr int NST  = 4;             // ring stages
constexpr int F4PC = TC * (Csz / 4);      // 512 float4 per stage
constexpr int STBY = F4PC * 16;           // 8192 bytes per stage
constexpr float LN2F = 0.69314718055994530942f;
constexpr float EPSF = 1e-7f;
}

__device__ __forceinline__ float ex2f_(float x) {
    float r; asm("ex2.approx.ftz.f32 %0, %1;" : "=f"(r) : "f"(x)); return r;
}
__device__ __forceinline__ float lg2f_(float x) {
    float r; asm("lg2.approx.ftz.f32 %0, %1;" : "=f"(r) : "f"(x)); return r;
}
__device__ __forceinline__ void cpasync16(uint32_t dst, const float4* src) {
    asm volatile("cp.async.cg.shared.global [%0], [%1], 16;" :: "r"(dst), "l"(src));
}
__device__ __forceinline__ void cpcommit() {
    asm volatile("cp.async.commit_group;");
}
template <int N> __device__ __forceinline__ void cpwait() {
    asm volatile("cp.async.wait_group %0;" :: "n"(N));
}

__global__ __launch_bounds__(128, 4)
void ctc_loss_kernel(const int* __restrict__ y_true,
                     const float* __restrict__ y_pred,
                     float* __restrict__ out)
{
    __shared__ float4 raw4[NST][F4PC];   // 32 KB ring
    __shared__ int    lab[Lsz];

    const int b    = blockIdx.x;
    const int tid  = threadIdx.x;
    const int wid  = tid >> 5;
    const int lane = tid & 31;
    const int rw   = (b / 148) & 3;     // co-resident CTAs -> different SMSPs

    if (tid < Lsz) lab[tid] = y_true[b * Lsz + tid];

    const bool isComp = (wid == rw);
    int lrank = 0;
    if (!isComp) lrank = ((wid > rw) ? wid - 1 : wid) * 32 + lane;  // 0..95

    const uint32_t rawBase = (uint32_t)__cvta_generic_to_shared(&raw4[0][0]);
    const float4*  src0    = (const float4*)(y_pred + (long)b * Tsz * Csz);

    auto issueChunk = [&](int c) {
        const float4* src = src0 + c * F4PC;
        uint32_t dst = rawBase + (uint32_t)(c & (NST - 1)) * STBY;
        #pragma unroll
        for (int i = lrank; i < F4PC; i += 96) cpasync16(dst + i * 16, src + i);
        cpcommit();
    };

    // prologue: stages 0..2 in flight; stage 0 complete before compute starts
    if (!isComp) {
        issueChunk(0); issueChunk(1); issueChunk(2);
        cpwait<2>();
    }
    __syncthreads();

    // recursion state (probability domain, per-lane frames)
    float a0 = 0.0f, a1 = 0.0f, a2 = 0.0f;
    float skipM = 0.0f, scaleRot = 1.0f, skipRotM = 0.0f;
    int   myLab = 0, laneSrc = 0, shift = 0;
    if (isComp) {
        myLab    = lab[lane];
        skipM    = (lane >= 1 && myLab != lab[lane - 1]) ? 1.0f : 0.0f;
        skipRotM = skipM;
        laneSrc  = (lane + 31) & 31;   // rotate: lane l <- lane (l-1)%32
    }

    for (int c = 0; c < NCH; ++c) {
        if (isComp) {
            const float* rawf = (const float*)&raw4[c & (NST - 1)][0];
            int t0 = 0;
            if (c == 0) {
                float pb = rawf[Csz - 1] + EPSF;
                float pl = rawf[myLab]   + EPSF;
                a0 = (lane == 0) ? pb : 0.0f;
                a1 = (lane == 0) ? pl : 0.0f;
                t0 = 1;
            }
            #pragma unroll
            for (int tt = t0; tt < TC; ++tt) {
                const float* row = rawf + tt * Csz;
                float pb = row[Csz - 1] + EPSF;   // blank prob (broadcast LDS)
                float pl = row[myLab]   + EPSF;   // label prob (scattered LDS)

                float raw = __shfl_sync(0xffffffffu, a1, laneSrc);
                float tsum = a1 + a0;

                // odd slot: a1 = (a1 + a0 + skip*alpha[2l-1]) * pl
                // (skipRotM = skipM * scaleRot, exact power-of-two folding)
                a1 = __fmaf_rn(raw, skipRotM, tsum) * pl;

                // even slot: lanes>=1 update a0; lane 0 updates a2 (s=64)
                float rot = raw * scaleRot;
                float x   = (lane == 0) ? a2 : a0;
                float r0  = (x + rot) * pb;
                if (lane == 0) { a2 = r0; a0 = a0 * pb; }
                else           { a0 = r0; }
            }

            if (c & 1) {
                // per-lane renorm + frame exchange (every 32 steps)
                float m = fmaxf(fmaxf(a0, a1), a2);   // a2==0 on lanes != 0
                int e = 0;
                if (m > 0.0f) e = (int)(__float_as_uint(m) >> 23) - 127;
                if (e > 126) e = 126;
                float sc = __uint_as_float((unsigned)(127 - e) << 23); // 2^-e
                a0 *= sc; a1 *= sc; a2 *= sc;
                shift += e;

                int shSrc = __shfl_sync(0xffffffffu, shift, laneSrc);
                if (m == 0.0f) shift = shSrc;       // dead lane adopts frame
                int d = shSrc - shift;
                d = (d > 126) ? 126 : d;
                scaleRot = (d < -126) ? 0.0f
                         : __uint_as_float((unsigned)(127 + d) << 23);  // 2^d
                skipRotM = skipM * scaleRot;
            }
        } else {
            if (c + 3 < NCH)      { issueChunk(c + 3); cpwait<2>(); }
            else if (c + 2 < NCH) { cpwait<1>(); }
            else if (c + 1 < NCH) { cpwait<0>(); }
        }
        __syncthreads();
    }

    if (isComp) {
        // log2 of alpha_T[S-1] (lane 0: a2) and alpha_T[S-2] (lane 31: a1)
        float v  = lg2f_((lane == 31) ? a1 : a2) + (float)shift;
        float v1 = __shfl_sync(0xffffffffu, v, 31);
        if (lane == 0) {
            float mm = fmaxf(v, v1);
            float dd = fabsf(v - v1);
            out[b] = -LN2F * (mm + lg2f_(1.0f + ex2f_(-dd)));
        }
    }
}

extern "C" void kernel_launch(void* const* d_in, const int* in_sizes, int n_in,
                              void* d_out, int out_size)
{
    const int*   y_true = (const int*)d_in[0];    // [512, 32] int32
    const float* y_pred = (const float*)d_in[1];  // [512, 512, 128] float32
    float*       out    = (float*)d_out;          // [512, 1] float32
    (void)in_sizes; (void)n_in; (void)out_size;

    ctc_loss_kernel<<<Bsz, 128>>>(y_true, y_pred, out);
}